// round 10
// baseline (speedup 1.0000x reference)
#include <cuda_runtime.h>
#include <cstdint>

// Problem constants (fixed shapes)
#define BQ    28800     // B*Q = 32*900
#define CNUM  92
#define TNUM  2048
#define RB    48        // rows per cost-block tile
#define RBLK  (BQ / RB) // 600 row blocks
#define PSTR  52        // padded row-stride (floats) of transposed prob tile in cost kernel
#define TSTR  49        // padded stride in prep transpose tile

// Scratch (allocation-free rule: __device__ globals)
__device__ __align__(16) float  g_probT[RBLK * CNUM * RB];  // (2 - softmax), [blk][c][i]
__device__ __align__(16) float4 g_tf[TNUM * 2];             // {cx,cy,wh,hh},{A4,label_bits,0,0}

// ---------------------------------------------------------------------------
// Packed f32x2 helpers (Blackwell sm_100+). NOTE: min/max.f32x2 do NOT exist.
// ---------------------------------------------------------------------------
union P2 { unsigned long long u; float2 f; };

__device__ __forceinline__ P2 mk2(float x, float y) { P2 r; r.f = make_float2(x, y); return r; }
__device__ __forceinline__ P2 add2(P2 a, P2 b) { P2 r; asm("add.rn.f32x2 %0,%1,%2;" : "=l"(r.u) : "l"(a.u), "l"(b.u)); return r; }
__device__ __forceinline__ P2 sub2(P2 a, P2 b) { P2 r; asm("sub.rn.f32x2 %0,%1,%2;" : "=l"(r.u) : "l"(a.u), "l"(b.u)); return r; }
__device__ __forceinline__ P2 mul2(P2 a, P2 b) { P2 r; asm("mul.rn.f32x2 %0,%1,%2;" : "=l"(r.u) : "l"(a.u), "l"(b.u)); return r; }
__device__ __forceinline__ P2 fma2(P2 a, P2 b, P2 c) { P2 r; asm("fma.rn.f32x2 %0,%1,%2,%3;" : "=l"(r.u) : "l"(a.u), "l"(b.u), "l"(c.u)); return r; }
__device__ __forceinline__ float frcp(float x) { float r; asm("rcp.approx.ftz.f32 %0,%1;" : "=f"(r) : "f"(x)); return r; }

// ---------------------------------------------------------------------------
// Phase 1: 600 blocks, one per 48-row cost tile. Warp-per-row softmax
// (no max-subtract: logits ~N(0,1); tol 1e-3), scatter (2-prob) into padded
// smem tile, coalesced float4 write-out. First 8 blocks also do targets.
// ---------------------------------------------------------------------------
__global__ __launch_bounds__(256) void prep_kernel(const float* __restrict__ logits,
                                                   const float* __restrict__ tgt_boxes,
                                                   const int*   __restrict__ tgt_labels) {
    __shared__ float sT[CNUM * TSTR];   // [c*49 + i], ~18 KB

    if (blockIdx.x < TNUM / 256) {
        int t = blockIdx.x * 256 + threadIdx.x;
        float4 b = reinterpret_cast<const float4*>(tgt_boxes)[t];
        g_tf[t * 2 + 0] = make_float4(b.x, b.y, 0.5f * b.z, 0.5f * b.w);
        g_tf[t * 2 + 1] = make_float4(4.f * b.z * b.w,
                                      __int_as_float(tgt_labels[t]), 0.f, 0.f);
    }

    const int warp = threadIdx.x >> 5;
    const int lane = threadIdx.x & 31;
    const int r0   = blockIdx.x * RB;

    // 8 warps x 6 rows = 48 rows
    #pragma unroll 1
    for (int k = 0; k < RB / 8; k++) {
        int i = warp + k * 8;
        const float* in = logits + (size_t)(r0 + i) * CNUM;

        float e0 = __expf(in[lane]);
        float e1 = __expf(in[lane + 32]);
        float e2 = (lane < 28) ? __expf(in[lane + 64]) : 0.f;

        float s = e0 + e1 + e2;
        #pragma unroll
        for (int o = 16; o > 0; o >>= 1) s += __shfl_xor_sync(0xffffffffu, s, o);
        float inv = __fdividef(1.f, s);

        sT[lane * TSTR + i]        = 2.f - e0 * inv;
        sT[(lane + 32) * TSTR + i] = 2.f - e1 * inv;
        if (lane < 28) sT[(lane + 64) * TSTR + i] = 2.f - e2 * inv;
    }
    __syncthreads();

    // Coalesced write-out into cost-kernel layout [blk][c][48]
    float4* gp = reinterpret_cast<float4*>(g_probT + (size_t)blockIdx.x * (CNUM * RB));
    #pragma unroll 1
    for (int j = threadIdx.x; j < CNUM * (RB / 4); j += 256) {
        int c = j / (RB / 4), q = j % (RB / 4);
        const float* s = sT + c * TSTR + q * 4;
        gp[j] = make_float4(s[0], s[1], s[2], s[3]);
    }
}

// ---------------------------------------------------------------------------
// Loop-invariant per-thread state: pack of 2 targets, all packed {A,B}.
// ---------------------------------------------------------------------------
struct TPack {
    P2 cx, cy, wh, hh, A4;   // center, HALF width/height, 4*area
};

// cost for 2 (row,target) pairs; ga/gb = pre-gathered (2 - prob[row][label]).
// Identity-based min/max: wiu*2 = S2-D, eW*2 = S2+D; 2x-scaled units throughout.
__device__ __forceinline__ float2 pack_cost(
    P2 rcx, P2 rcy, P2 rwh, P2 rhh, P2 rA4,
    const TPack& T, float ga, float gb, P2 cm2)
{
    P2 dcx = sub2(rcx, T.cx);
    P2 dcy = sub2(rcy, T.cy);
    P2 dwh = sub2(rwh, T.wh);
    P2 dhh = sub2(rhh, T.hh);

    // L1 = |dcx|+|dcy| + 2(|dwh|+|dhh|); base = g + 5*L1
    float c1a = fabsf(dcx.f.x) + fabsf(dcy.f.x);
    float c1b = fabsf(dcx.f.y) + fabsf(dcy.f.y);
    float w1a = fabsf(dwh.f.x) + fabsf(dhh.f.x);
    float w1b = fabsf(dwh.f.y) + fabsf(dhh.f.y);
    float basea = fmaf(5.f, c1a, fmaf(10.f, w1a, ga));
    float baseb = fmaf(5.f, c1b, fmaf(10.f, w1b, gb));

    // x dimension
    P2 d1x = add2(dcx, dwh);
    P2 d0x = sub2(dcx, dwh);
    P2 Dx  = mk2(fabsf(d1x.f.x) + fabsf(d0x.f.x),
                 fabsf(d1x.f.y) + fabsf(d0x.f.y));
    P2 sx  = add2(rwh, T.wh);
    P2 Sx  = add2(sx, sx);
    P2 wiu = sub2(Sx, Dx);
    P2 eW  = add2(Sx, Dx);

    // y dimension
    P2 d1y = add2(dcy, dhh);
    P2 d0y = sub2(dcy, dhh);
    P2 Dy  = mk2(fabsf(d1y.f.x) + fabsf(d0y.f.x),
                 fabsf(d1y.f.y) + fabsf(d0y.f.y));
    P2 sy  = add2(rhh, T.hh);
    P2 Sy  = add2(sy, sy);
    P2 hiu = sub2(Sy, Dy);
    P2 eH  = add2(Sy, Dy);

    P2 inter = mul2(mk2(fmaxf(wiu.f.x, 0.f), fmaxf(wiu.f.y, 0.f)),
                    mk2(fmaxf(hiu.f.x, 0.f), fmaxf(hiu.f.y, 0.f)));
    P2 E  = mul2(eW, eH);
    P2 U4 = sub2(add2(rA4, T.A4), inter);

    P2 num = fma2(inter, E, mul2(U4, U4));
    P2 nm  = mul2(num, cm2);           // pre-scale by -2 (packed)
    P2 den = mul2(U4, E);

    float resa = fmaf(nm.f.x, frcp(den.f.x), basea);
    float resb = fmaf(nm.f.y, frcp(den.f.y), baseb);
    return make_float2(resa, resb);
}

// ---------------------------------------------------------------------------
// Phase 2: main cost kernel. 256 threads, 8 targets/thread (4 independent
// packs -> 2x ILP vs before). One block covers all 2048 targets x 48 rows.
// 600 blocks = 2.03 balanced waves at occ 2.
// ---------------------------------------------------------------------------
__global__ __launch_bounds__(256, 2) void cost_kernel(const float* __restrict__ pred_boxes,
                                                      float* __restrict__ out) {
    __shared__ float sProbT[CNUM * PSTR];   // 92*52*4 = 19136 B  [c*PSTR + i]
    __shared__ float sDup[RB * 10];         // {cx,cx,cy,cy,wh,wh,hh,hh,A4,A4}

    const int tid = threadIdx.x;
    const int r0  = blockIdx.x * RB;
    const int t0  = tid * 8;

    // Stage transposed prob tile (contiguous float4 reads, padded STS)
    {
        const float4* gp = reinterpret_cast<const float4*>(
            g_probT + (size_t)blockIdx.x * (CNUM * RB));
        float4* sp = reinterpret_cast<float4*>(sProbT);
        #pragma unroll 1
        for (int j = tid; j < CNUM * (RB / 4); j += 256) {
            int c = j / (RB / 4), i4 = j % (RB / 4);
            sp[c * (PSTR / 4) + i4] = gp[j];
        }
    }
    // Row features (duplicated for packed math): center, half-extents, 4*area
    if (tid < RB) {
        float4 b = reinterpret_cast<const float4*>(pred_boxes)[r0 + tid];
        float* d = sDup + tid * 10;
        d[0] = d[1] = b.x;          d[2] = d[3] = b.y;
        d[4] = d[5] = 0.5f * b.z;   d[6] = d[7] = 0.5f * b.w;
        float a4 = 4.f * b.z * b.w; d[8] = d[9] = a4;
    }
    __syncthreads();

    // Loop-invariant target packs + labels (4 packs = 8 targets)
    TPack T[4];
    int gidx[8];
    #pragma unroll
    for (int p = 0; p < 4; p++) {
        int ta = t0 + p * 2, tb = ta + 1;
        float4 A0 = g_tf[ta * 2 + 0], A1 = g_tf[ta * 2 + 1];
        float4 B0 = g_tf[tb * 2 + 0], B1 = g_tf[tb * 2 + 1];
        T[p].cx = mk2(A0.x, B0.x); T[p].cy = mk2(A0.y, B0.y);
        T[p].wh = mk2(A0.z, B0.z); T[p].hh = mk2(A0.w, B0.w);
        T[p].A4 = mk2(A1.x, B1.x);
        gidx[p * 2 + 0] = __float_as_int(A1.y) * (PSTR / 4);
        gidx[p * 2 + 1] = __float_as_int(B1.y) * (PSTR / 4);
    }

    const P2 cm2 = mk2(-2.f, -2.f);
    const float4* probT4 = reinterpret_cast<const float4*>(sProbT);

    float4* op = reinterpret_cast<float4*>(out + (size_t)r0 * TNUM + t0);
    const int strideF4 = TNUM / 4;

    #pragma unroll 1
    for (int w = 0; w < RB / 4; w++) {
        // 4 rows of gathered class costs, one LDS.128 per target
        float4 g[8];
        #pragma unroll
        for (int q = 0; q < 8; q++) g[q] = probT4[gidx[q] + w];
        float gv[8][4];
        #pragma unroll
        for (int q = 0; q < 8; q++) {
            gv[q][0] = g[q].x; gv[q][1] = g[q].y; gv[q][2] = g[q].z; gv[q][3] = g[q].w;
        }

        #pragma unroll
        for (int k = 0; k < 4; k++) {
            const int i = w * 4 + k;
            const P2* rp = reinterpret_cast<const P2*>(sDup + i * 10);
            P2 rcx = rp[0], rcy = rp[1], rwh = rp[2], rhh = rp[3], rA4 = rp[4];

            float2 r0v = pack_cost(rcx, rcy, rwh, rhh, rA4, T[0], gv[0][k], gv[1][k], cm2);
            float2 r1v = pack_cost(rcx, rcy, rwh, rhh, rA4, T[1], gv[2][k], gv[3][k], cm2);
            float2 r2v = pack_cost(rcx, rcy, rwh, rhh, rA4, T[2], gv[4][k], gv[5][k], cm2);
            float2 r3v = pack_cost(rcx, rcy, rwh, rhh, rA4, T[3], gv[6][k], gv[7][k], cm2);

            op[(size_t)i * strideF4 + 0] = make_float4(r0v.x, r0v.y, r1v.x, r1v.y);
            op[(size_t)i * strideF4 + 1] = make_float4(r2v.x, r2v.y, r3v.x, r3v.y);
        }
    }
}

// ---------------------------------------------------------------------------
extern "C" void kernel_launch(void* const* d_in, const int* in_sizes, int n_in,
                              void* d_out, int out_size) {
    const float* logits  = (const float*)d_in[0];   // [32,900,92] f32
    const float* pboxes  = (const float*)d_in[1];   // [32,900,4]  f32
    const int*   tlabels = (const int*)  d_in[2];   // [2048] i32
    const float* tboxes  = (const float*)d_in[3];   // [2048,4] f32
    float* out = (float*)d_out;                      // [32,900,2048] f32

    prep_kernel<<<RBLK, 256>>>(logits, tboxes, tlabels);   // 600 blocks

    cost_kernel<<<RBLK, 256>>>(pboxes, out);               // 600 blocks
}

// round 11
// speedup vs baseline: 1.1565x; 1.1565x over previous
#include <cuda_runtime.h>
#include <cstdint>

// Problem constants (fixed shapes)
#define BQ    28800     // B*Q = 32*900
#define CNUM  92
#define TNUM  2048
#define RB    96        // rows per cost-block tile (best measured config)
#define RBLK  (BQ / RB) // 300 row blocks
#define PSTR  100       // padded row-stride (floats) of transposed prob tile in cost kernel
#define HROW  48        // rows per prep block (2 prep blocks per cost block)
#define TSTR  49        // padded stride in prep transpose tile

// Scratch (allocation-free rule: __device__ globals)
// Transposed prob: [block][class][row_in_block] holding (2 - softmax)
__device__ __align__(16) float  g_probT[RBLK * CNUM * RB];
__device__ __align__(16) float4 g_tf[TNUM * 3];   // {cx,cy,w,h},{x0,y0,x1,y1},{area,label_bits,0,0}

// ---------------------------------------------------------------------------
// Packed f32x2 helpers (Blackwell sm_100+). NOTE: min/max.f32x2 do NOT exist.
// ---------------------------------------------------------------------------
union P2 { unsigned long long u; float2 f; };

__device__ __forceinline__ P2 mk2(float x, float y) { P2 r; r.f = make_float2(x, y); return r; }
__device__ __forceinline__ P2 add2(P2 a, P2 b) { P2 r; asm("add.rn.f32x2 %0,%1,%2;" : "=l"(r.u) : "l"(a.u), "l"(b.u)); return r; }
__device__ __forceinline__ P2 sub2(P2 a, P2 b) { P2 r; asm("sub.rn.f32x2 %0,%1,%2;" : "=l"(r.u) : "l"(a.u), "l"(b.u)); return r; }
__device__ __forceinline__ P2 mul2(P2 a, P2 b) { P2 r; asm("mul.rn.f32x2 %0,%1,%2;" : "=l"(r.u) : "l"(a.u), "l"(b.u)); return r; }
__device__ __forceinline__ P2 fma2(P2 a, P2 b, P2 c) { P2 r; asm("fma.rn.f32x2 %0,%1,%2,%3;" : "=l"(r.u) : "l"(a.u), "l"(b.u), "l"(c.u)); return r; }
__device__ __forceinline__ float frcp(float x) { float r; asm("rcp.approx.ftz.f32 %0,%1;" : "=f"(r) : "f"(x)); return r; }

// ---------------------------------------------------------------------------
// Phase 1: 600 blocks, each does 48 rows of one 96-row cost tile.
// Warp-per-row softmax (no max-subtract: logits ~N(0,1); tol 1e-3),
// scatter (2-prob) into padded smem tile, coalesced float4 write-out.
// First 8 blocks also precompute per-target features.
// ---------------------------------------------------------------------------
__global__ __launch_bounds__(256) void prep_kernel(const float* __restrict__ logits,
                                                   const float* __restrict__ tgt_boxes,
                                                   const int*   __restrict__ tgt_labels) {
    __shared__ float sT[CNUM * TSTR];   // [c*49 + i], ~18 KB

    if (blockIdx.x < TNUM / 256) {
        int t = blockIdx.x * 256 + threadIdx.x;
        float4 b = reinterpret_cast<const float4*>(tgt_boxes)[t];
        float hw = 0.5f * b.z, hh = 0.5f * b.w;
        g_tf[t * 3 + 0] = b;
        g_tf[t * 3 + 1] = make_float4(b.x - hw, b.y - hh, b.x + hw, b.y + hh);
        g_tf[t * 3 + 2] = make_float4(b.z * b.w, __int_as_float(tgt_labels[t]), 0.f, 0.f);
    }

    const int warp = threadIdx.x >> 5;
    const int lane = threadIdx.x & 31;
    const int r0   = blockIdx.x * HROW;              // global row base (48-row granule)
    const int cblk = blockIdx.x >> 1;                // cost block index
    const int half = blockIdx.x & 1;

    // 8 warps x 6 rows = 48 rows
    #pragma unroll 1
    for (int k = 0; k < HROW / 8; k++) {
        int i = warp + k * 8;                        // row in half-tile
        const float* in = logits + (size_t)(r0 + i) * CNUM;

        float e0 = __expf(in[lane]);
        float e1 = __expf(in[lane + 32]);
        float e2 = (lane < 28) ? __expf(in[lane + 64]) : 0.f;

        float s = e0 + e1 + e2;
        #pragma unroll
        for (int o = 16; o > 0; o >>= 1) s += __shfl_xor_sync(0xffffffffu, s, o);
        float inv = __fdividef(1.f, s);

        sT[lane * TSTR + i]        = 2.f - e0 * inv;
        sT[(lane + 32) * TSTR + i] = 2.f - e1 * inv;
        if (lane < 28) sT[(lane + 64) * TSTR + i] = 2.f - e2 * inv;
    }
    __syncthreads();

    // Coalesced write-out into the cost-kernel layout [cblk][c][96]
    float* gbase = g_probT + (size_t)cblk * (CNUM * RB) + half * HROW;
    #pragma unroll 1
    for (int j = threadIdx.x; j < CNUM * (HROW / 4); j += 256) {
        int c = j / (HROW / 4), q = j % (HROW / 4);
        const float* s = sT + c * TSTR + q * 4;
        *reinterpret_cast<float4*>(gbase + (size_t)c * RB + q * 4) =
            make_float4(s[0], s[1], s[2], s[3]);
    }
}

// ---------------------------------------------------------------------------
// Loop-invariant per-thread state: pack of 2 targets. (R4 best-measured form)
// ---------------------------------------------------------------------------
struct TPack {
    P2 cx, cy, w, h, area;          // packed {A,B}
    float ax0, ay0, ax1, ay1;       // target A xyxy (scalar FMNMX path)
    float bx0, by0, bx1, by1;       // target B xyxy
};

// cost for 2 (row,target) pairs; ga/gb = pre-gathered (2 - prob[row][label]).
__device__ __forceinline__ float2 pack_cost(
    P2 rcx, P2 rcy, P2 rw, P2 rh, P2 rA, float4 rx,
    const TPack& T, float ga, float gb)
{
    // L1: packed subs, scalar abs-adds (abs folds into FADD src modifiers)
    P2 d0 = sub2(rcx, T.cx);
    P2 d1 = sub2(rcy, T.cy);
    P2 d2 = sub2(rw,  T.w);
    P2 d3 = sub2(rh,  T.h);
    float l1a = (fabsf(d0.f.x) + fabsf(d1.f.x)) + (fabsf(d2.f.x) + fabsf(d3.f.x));
    float l1b = (fabsf(d0.f.y) + fabsf(d1.f.y)) + (fabsf(d2.f.y) + fabsf(d3.f.y));

    // Intersection widths (scalar FMNMX), enclosing via eW = (rw+tw) - wiu
    float wiua = fminf(rx.z, T.ax1) - fmaxf(rx.x, T.ax0);
    float wiub = fminf(rx.z, T.bx1) - fmaxf(rx.x, T.bx0);
    float wa = fmaxf(wiua, 0.f), wb = fmaxf(wiub, 0.f);
    P2 eW = sub2(add2(rw, T.w), mk2(wiua, wiub));

    float hiua = fminf(rx.w, T.ay1) - fmaxf(rx.y, T.ay0);
    float hiub = fminf(rx.w, T.by1) - fmaxf(rx.y, T.by0);
    float ha = fmaxf(hiua, 0.f), hb = fmaxf(hiub, 0.f);
    P2 eH = sub2(add2(rh, T.h), mk2(hiua, hiub));

    P2 inter = mul2(mk2(wa, wb), mk2(ha, hb));
    P2 E     = mul2(eW, eH);
    P2 uni   = sub2(add2(rA, T.area), inter);

    // inter/uni + uni/E == (inter*E + uni^2) / (uni*E)  -> one rcp per pair
    P2 num = fma2(inter, E, mul2(uni, uni));
    P2 den = mul2(uni, E);

    float ra = frcp(den.f.x);
    float rb = frcp(den.f.y);
    float resa = fmaf(-2.f, num.f.x * ra, fmaf(5.f, l1a, ga));
    float resb = fmaf(-2.f, num.f.y * rb, fmaf(5.f, l1b, gb));
    return make_float2(resa, resb);
}

// ---------------------------------------------------------------------------
// Phase 2: main cost kernel — EXACT best-measured config (66.1 us):
// RB=96, occ 2, 4 targets/thread (2 packs), sDup LDS.64->P2, no prefetch.
// ---------------------------------------------------------------------------
__global__ __launch_bounds__(256, 2) void cost_kernel(const float* __restrict__ pred_boxes,
                                                      float* __restrict__ out) {
    __shared__ float  sProbT[CNUM * PSTR];  // 36800 B  [c*PSTR + i]
    __shared__ float  sDup[RB * 10];        // {cx,cx,cy,cy,w,w,h,h,A,A}
    __shared__ float4 sXY[RB];              // row xyxy

    const int tid = threadIdx.x;
    const int r0  = blockIdx.x * RB;
    const int t0  = blockIdx.y * 1024 + tid * 4;

    // Stage transposed prob tile (contiguous float4 reads, padded STS)
    {
        const float4* gp = reinterpret_cast<const float4*>(
            g_probT + (size_t)blockIdx.x * (CNUM * RB));
        float4* sp = reinterpret_cast<float4*>(sProbT);
        #pragma unroll 1
        for (int j = tid; j < CNUM * (RB / 4); j += 256) {
            int c = j / (RB / 4), i4 = j % (RB / 4);
            sp[c * (PSTR / 4) + i4] = gp[j];
        }
    }
    // Row features (duplicated for packed math) + xyxy
    if (tid < RB) {
        float4 b = reinterpret_cast<const float4*>(pred_boxes)[r0 + tid];
        float* d = sDup + tid * 10;
        d[0] = d[1] = b.x;  d[2] = d[3] = b.y;
        d[4] = d[5] = b.z;  d[6] = d[7] = b.w;
        float a = b.z * b.w; d[8] = d[9] = a;
        float hw = 0.5f * b.z, hh = 0.5f * b.w;
        sXY[tid] = make_float4(b.x - hw, b.y - hh, b.x + hw, b.y + hh);
    }
    __syncthreads();

    // Loop-invariant target packs + labels
    TPack T0, T1;
    int lab[4];
    #pragma unroll
    for (int p = 0; p < 2; p++) {
        TPack& T = p ? T1 : T0;
        int ta = t0 + p * 2, tb = ta + 1;
        float4 A0 = g_tf[ta * 3 + 0], A1 = g_tf[ta * 3 + 1], A2 = g_tf[ta * 3 + 2];
        float4 B0 = g_tf[tb * 3 + 0], B1 = g_tf[tb * 3 + 1], B2 = g_tf[tb * 3 + 2];
        T.cx = mk2(A0.x, B0.x); T.cy = mk2(A0.y, B0.y);
        T.w  = mk2(A0.z, B0.z); T.h  = mk2(A0.w, B0.w);
        T.area = mk2(A2.x, B2.x);
        T.ax0 = A1.x; T.ay0 = A1.y; T.ax1 = A1.z; T.ay1 = A1.w;
        T.bx0 = B1.x; T.by0 = B1.y; T.bx1 = B1.z; T.by1 = B1.w;
        lab[p * 2 + 0] = __float_as_int(A2.y);
        lab[p * 2 + 1] = __float_as_int(B2.y);
    }

    const float4* probT4 = reinterpret_cast<const float4*>(sProbT);
    const int gidx0 = lab[0] * (PSTR / 4);
    const int gidx1 = lab[1] * (PSTR / 4);
    const int gidx2 = lab[2] * (PSTR / 4);
    const int gidx3 = lab[3] * (PSTR / 4);

    float4* op = reinterpret_cast<float4*>(out + (size_t)r0 * TNUM + t0);
    const int strideF4 = TNUM / 4;

    #pragma unroll 1
    for (int w = 0; w < RB / 4; w++) {
        // 4 rows of gathered class costs, one LDS.128 per target
        float4 gA = probT4[gidx0 + w];
        float4 gB = probT4[gidx1 + w];
        float4 gC = probT4[gidx2 + w];
        float4 gD = probT4[gidx3 + w];
        float gAa[4] = {gA.x, gA.y, gA.z, gA.w};
        float gBa[4] = {gB.x, gB.y, gB.z, gB.w};
        float gCa[4] = {gC.x, gC.y, gC.z, gC.w};
        float gDa[4] = {gD.x, gD.y, gD.z, gD.w};

        #pragma unroll
        for (int k = 0; k < 4; k++) {
            const int i = w * 4 + k;
            const P2* rp = reinterpret_cast<const P2*>(sDup + i * 10);
            P2 rcx = rp[0], rcy = rp[1], rw = rp[2], rh = rp[3], rA = rp[4];
            float4 rx = sXY[i];

            float2 resA = pack_cost(rcx, rcy, rw, rh, rA, rx, T0, gAa[k], gBa[k]);
            float2 resB = pack_cost(rcx, rcy, rw, rh, rA, rx, T1, gCa[k], gDa[k]);

            op[(size_t)i * strideF4] = make_float4(resA.x, resA.y, resB.x, resB.y);
        }
    }
}

// ---------------------------------------------------------------------------
extern "C" void kernel_launch(void* const* d_in, const int* in_sizes, int n_in,
                              void* d_out, int out_size) {
    const float* logits  = (const float*)d_in[0];   // [32,900,92] f32
    const float* pboxes  = (const float*)d_in[1];   // [32,900,4]  f32
    const int*   tlabels = (const int*)  d_in[2];   // [2048] i32
    const float* tboxes  = (const float*)d_in[3];   // [2048,4] f32
    float* out = (float*)d_out;                      // [32,900,2048] f32

    prep_kernel<<<BQ / HROW, 256>>>(logits, tboxes, tlabels);   // 600 blocks

    dim3 grid(RBLK, TNUM / 1024);  // (300, 2) = 600 blocks
    cost_kernel<<<grid, 256>>>(pboxes, out);
}